// round 6
// baseline (speedup 1.0000x reference)
#include <cuda_runtime.h>
#include <math.h>

#define D     32
#define GMAX  64
#define NMAX  100000
#define EMAX  1600000

// -------- device scratch: referenced ONLY from device code --------
__device__ __align__(16) float g_agg[2][NMAX * D]; // per-layer aggregation results
__device__ __align__(16) float g_x1[NMAX * D];     // layer-1 node features
__device__ unsigned g_max[3 * GMAX * D];           // per-layer segment-max (encoded)
__device__ float    g_Wf[5 * D * D];               // BN-folded: lin0,lin1,lin2,conv0,conv1
__device__ float    g_bf[5 * D];
__device__ int      g_deg[NMAX];                   // in-degree histogram
__device__ int      g_off[NMAX + 1];               // CSR row offsets (by dst)
__device__ int      g_cur[NMAX];                   // fill cursors
__device__ int      g_csr[EMAX];                   // src ids grouped by dst

// monotone float <-> uint mapping so atomicMax(unsigned) == float max
__device__ __forceinline__ unsigned fenc(float f) {
    unsigned u = __float_as_uint(f);
    return (u & 0x80000000u) ? ~u : (u | 0x80000000u);
}
__device__ __forceinline__ float fdec(unsigned k) {
    return __uint_as_float((k & 0x80000000u) ? (k ^ 0x80000000u) : ~k);
}
__device__ __forceinline__ float elu1(float h) { return h > 0.f ? h : expm1f(h); }

// -------- prep: fold BN into W,b ; init max buffers ; zero degree histogram --------
__global__ void prep_kernel(const float* __restrict__ linW,  const float* __restrict__ linb,
                            const float* __restrict__ ling,  const float* __restrict__ linbe,
                            const float* __restrict__ linm,  const float* __restrict__ linv,
                            const float* __restrict__ convW, const float* __restrict__ convb,
                            const float* __restrict__ convg, const float* __restrict__ convbe,
                            const float* __restrict__ convm, const float* __restrict__ convv,
                            int N) {
    int t = blockIdx.x * blockDim.x + threadIdx.x;

    if (t < D * D) {
        #pragma unroll
        for (int m = 0; m < 5; m++) {
            const float *W, *b, *g, *be, *mu, *va;
            if (m < 3) {
                W = linW + m*D*D;  b = linb + m*D;  g = ling + m*D;
                be = linbe + m*D;  mu = linm + m*D; va = linv + m*D;
            } else {
                int l = m - 3;
                W = convW + l*D*D; b = convb + l*D; g = convg + l*D;
                be = convbe + l*D; mu = convm + l*D; va = convv + l*D;
            }
            int col = t & (D - 1);
            float sc = g[col] * rsqrtf(va[col] + 1e-5f);
            g_Wf[m*D*D + t] = W[t] * sc;
            if (t < D) g_bf[m*D + t] = (b[t] - mu[t]) * sc + be[t];
        }
    }
    if (t < 3*GMAX*D) g_max[t] = 0x007FFFFFu;   // encode(-inf)
    if (t < N) g_deg[t] = 0;
}

// -------- CSR build: histogram of dst --------
__global__ void hist_kernel(const int* __restrict__ ei, int E) {
    int e = blockIdx.x * blockDim.x + threadIdx.x;
    if (e < E) atomicAdd(&g_deg[ei[E + e]], 1);
}

// -------- CSR build: 1-block exclusive scan over deg -> g_off, g_cur --------
__global__ void scan_kernel(int N) {
    __shared__ int sm[1024];
    int t = threadIdx.x;
    int chunk = (N + 1023) / 1024;
    int lo = t * chunk, hi = min(lo + chunk, N);
    int sum = 0;
    for (int i = lo; i < hi; i++) sum += g_deg[i];
    sm[t] = sum;
    __syncthreads();
    for (int off = 1; off < 1024; off <<= 1) {
        int v = (t >= off) ? sm[t - off] : 0;
        __syncthreads();
        sm[t] += v;
        __syncthreads();
    }
    int base = (t == 0) ? 0 : sm[t - 1];
    for (int i = lo; i < hi; i++) {
        g_off[i] = base;
        g_cur[i] = base;
        base += g_deg[i];
    }
    if (t == 1023) g_off[N] = base;
}

// -------- CSR build: fill src ids grouped by dst --------
__global__ void fill_kernel(const int* __restrict__ ei, int E) {
    int e = blockIdx.x * blockDim.x + threadIdx.x;
    if (e >= E) return;
    int s = ei[e];
    int d = ei[E + e];
    int pos = atomicAdd(&g_cur[d], 1);
    g_csr[pos] = s;
}

// -------- aggregation via CSR gather: g_agg[L][node] = sum_{s in row(node)} x[s] --------
// Broadcast index loads (all lanes same address), unroll-8 independent row gathers.
// L=0: sources from input x (arg). L=1: sources from g_x1 (device symbol).
template <int L>
__global__ void __launch_bounds__(256)
agg_kernel(const float* __restrict__ xarg, int N) {
    const float* __restrict__ x = (L == 0) ? xarg : g_x1;
    int t = threadIdx.x;
    int node = (blockIdx.x * 256 + t) >> 5;
    int lane = t & 31;
    if (node >= N) return;

    int rs = g_off[node], re = g_off[node + 1];
    float acc = 0.f;
    int k = rs;
    for (; k + 8 <= re; k += 8) {
        int i0 = g_csr[k],     i1 = g_csr[k + 1], i2 = g_csr[k + 2], i3 = g_csr[k + 3];
        int i4 = g_csr[k + 4], i5 = g_csr[k + 5], i6 = g_csr[k + 6], i7 = g_csr[k + 7];
        float v0 = x[i0*D + lane], v1 = x[i1*D + lane];
        float v2 = x[i2*D + lane], v3 = x[i3*D + lane];
        float v4 = x[i4*D + lane], v5 = x[i5*D + lane];
        float v6 = x[i6*D + lane], v7 = x[i7*D + lane];
        acc += ((v0 + v1) + (v2 + v3)) + ((v4 + v5) + (v6 + v7));
    }
    for (; k < re; k++) acc += x[g_csr[k]*D + lane];
    g_agg[L][node*D + lane] = acc;
}

// -------- fused GIN layer (aggregation precomputed in g_agg[layer]) --------
// FIRST (layer 1): reads x (arg), writes x1 -> g_x1 (symbol)
//   z0 = ELU(x@W0'), x1 = ELU((x+agg0)@Wc0'), z1 = lw1*ELU(x1@Wl1')
//   Z = lw0*z0 + z1, segmax(z0-raw), segmax(z1)
// !FIRST (layer 2): reads g_x1 (symbol), writes x2 -> xout (arg, d_out)
//   x2 = ELU((x1+agg1)@Wc1'), z2 = lw2*ELU(x2@Wl2'); Z += z2; segmax(z2)
template <bool FIRST>
__global__ void __launch_bounds__(256)
fused_kernel(const float* __restrict__ xarg, float* __restrict__ xoutarg,
             const int* __restrict__ batch, const float* __restrict__ lw,
             float* __restrict__ Zbuf, int N) {
    constexpr int cm = FIRST ? 3 : 4;   // conv weight slot
    constexpr int lm = FIRST ? 1 : 2;   // lin weight slot
    __shared__ float Wc[D*D], Wl[D*D], W0[FIRST ? D*D : 1];
    __shared__ float bc[D], bl[D], b0[D];
    int t = threadIdx.x;
    for (int i = t; i < D*D; i += 256) {
        Wc[i] = g_Wf[cm*D*D + i];
        Wl[i] = g_Wf[lm*D*D + i];
        if (FIRST) W0[i] = g_Wf[i];
    }
    if (t < D) {
        bc[t] = g_bf[cm*D + t];
        bl[t] = g_bf[lm*D + t];
        if (FIRST) b0[t] = g_bf[t];
    }
    __syncthreads();

    int node = (blockIdx.x * 256 + t) >> 5;
    int lane = t & 31;
    if (node >= N) return;

    const float* xin  = FIRST ? xarg : g_x1;
    float*       xout = FIRST ? g_x1 : xoutarg;
    const float* agg  = g_agg[FIRST ? 0 : 1];

    float xself = xin[node*D + lane];
    float acc = xself + agg[node*D + lane];
    int seg = batch[node];

    // ---- optional layer-0 lin-MLP on raw x ----
    float Zval = 0.f;
    if (FIRST) {
        float h0 = b0[lane];
        #pragma unroll
        for (int k = 0; k < D; k++)
            h0 = fmaf(__shfl_sync(0xffffffffu, xself, k), W0[k*D + lane], h0);
        float z0 = elu1(h0);
        Zval = lw[0] * z0;
        atomicMax(&g_max[seg*D + lane], fenc(z0));       // layer0 max over RAW z0
    }

    // ---- conv MLP: x' = ELU(BNfold(acc @ Wc)) ----
    float h = bc[lane];
    #pragma unroll
    for (int k = 0; k < D; k++)
        h = fmaf(__shfl_sync(0xffffffffu, acc, k), Wc[k*D + lane], h);
    float xn = elu1(h);
    xout[node*D + lane] = xn;

    // ---- lin MLP: z = lw * ELU(BNfold(x' @ Wl)) ----
    float h2 = bl[lane];
    #pragma unroll
    for (int k = 0; k < D; k++)
        h2 = fmaf(__shfl_sync(0xffffffffu, xn, k), Wl[k*D + lane], h2);
    constexpr int l = FIRST ? 1 : 2;
    float z = lw[l] * elu1(h2);

    if (FIRST) Zbuf[node*D + lane] = Zval + z;
    else       Zbuf[node*D + lane] += z;
    atomicMax(&g_max[l*GMAX*D + seg*D + lane], fenc(z));
}

// -------- out = sum of the three per-layer segment maxes --------
__global__ void final_kernel(float* __restrict__ out) {
    int i = blockIdx.x * blockDim.x + threadIdx.x;
    if (i < GMAX*D)
        out[i] = fdec(g_max[i]) + fdec(g_max[GMAX*D + i]) + fdec(g_max[2*GMAX*D + i]);
}

extern "C" void kernel_launch(void* const* d_in, const int* in_sizes, int n_in,
                              void* d_out, int out_size) {
    const float* x      = (const float*)d_in[0];
    const int*   ei     = (const int*)d_in[1];      // int32 (JAX x64 disabled)
    const int*   batch  = (const int*)d_in[2];
    const float* lw     = (const float*)d_in[3];
    const float* linW   = (const float*)d_in[4];
    const float* linb   = (const float*)d_in[5];
    const float* ling   = (const float*)d_in[6];
    const float* linbe  = (const float*)d_in[7];
    const float* linm   = (const float*)d_in[8];
    const float* linv   = (const float*)d_in[9];
    const float* convW  = (const float*)d_in[10];
    const float* convb  = (const float*)d_in[11];
    const float* convg  = (const float*)d_in[12];
    const float* convbe = (const float*)d_in[13];
    const float* convm  = (const float*)d_in[14];
    const float* convv  = (const float*)d_in[15];

    int N = in_sizes[0] / D;
    int E = in_sizes[1] / 2;

    float* out = (float*)d_out;            // [G*D]
    float* Z   = out + GMAX * D;           // [N*D]
    float* xb  = Z + (size_t)N * D;        // [N*D] final x output

    int node_blocks = (N * 32 + 255) / 256;
    int e_blocks = (E + 255) / 256;
    int prep_n = N > 5*D*D ? N : 5*D*D;

    prep_kernel<<<(prep_n + 1023) / 1024, 1024>>>(linW, linb, ling, linbe, linm, linv,
                                                  convW, convb, convg, convbe, convm, convv, N);

    // CSR build (shared by both layers)
    hist_kernel<<<e_blocks, 256>>>(ei, E);
    scan_kernel<<<1, 1024>>>(N);
    fill_kernel<<<e_blocks, 256>>>(ei, E);

    // layer 1: gather-agg(x) -> g_agg[0]; fused l0 + conv0 + lin1 (x -> g_x1)
    agg_kernel<0><<<node_blocks, 256>>>(x, N);
    fused_kernel<true><<<node_blocks, 256>>>(x, nullptr, batch, lw, Z, N);

    // layer 2: gather-agg(g_x1) -> g_agg[1]; fused conv1 + lin2 (g_x1 -> xb)
    agg_kernel<1><<<node_blocks, 256>>>(nullptr, N);
    fused_kernel<false><<<node_blocks, 256>>>(nullptr, xb, batch, lw, Z, N);

    final_kernel<<<(GMAX*D + 255) / 256, 256>>>(out);
}

// round 7
// speedup vs baseline: 1.5738x; 1.5738x over previous
#include <cuda_runtime.h>
#include <math.h>

#define D     32
#define GMAX  64
#define NMAX  100000
#define EMAX  1600000
#define TILE  1024
#define NBMAX ((NMAX + TILE - 1) / TILE)   // 98

// -------- device scratch: referenced ONLY from device code --------
__device__ __align__(16) float g_agg[NMAX * D];    // aggregation result (overwritten per layer)
__device__ __align__(16) float g_x1[NMAX * D];     // layer-1 node features
__device__ unsigned g_max[3 * GMAX * D];           // per-layer segment-max (encoded)
__device__ float    g_Wf[5 * D * D];               // BN-folded: lin0,lin1,lin2,conv0,conv1
__device__ float    g_bf[5 * D];
__device__ int      g_deg[NMAX];                   // in-degree histogram
__device__ int      g_off[NMAX + 1];               // CSR row offsets (by dst)
__device__ int      g_cur[NMAX];                   // fill cursors
__device__ int      g_csr[EMAX];                   // src ids grouped by dst
__device__ int      g_bsum[NBMAX];                 // per-tile sums
__device__ int      g_boff[NBMAX];                 // per-tile exclusive offsets

// monotone float <-> uint mapping so atomicMax(unsigned) == float max
__device__ __forceinline__ unsigned fenc(float f) {
    unsigned u = __float_as_uint(f);
    return (u & 0x80000000u) ? ~u : (u | 0x80000000u);
}
__device__ __forceinline__ float fdec(unsigned k) {
    return __uint_as_float((k & 0x80000000u) ? (k ^ 0x80000000u) : ~k);
}
__device__ __forceinline__ float elu1(float h) { return h > 0.f ? h : expm1f(h); }

// -------- prep: fold BN into W,b ; init max buffers ; zero degree histogram --------
__global__ void prep_kernel(const float* __restrict__ linW,  const float* __restrict__ linb,
                            const float* __restrict__ ling,  const float* __restrict__ linbe,
                            const float* __restrict__ linm,  const float* __restrict__ linv,
                            const float* __restrict__ convW, const float* __restrict__ convb,
                            const float* __restrict__ convg, const float* __restrict__ convbe,
                            const float* __restrict__ convm, const float* __restrict__ convv,
                            int N) {
    int t = blockIdx.x * blockDim.x + threadIdx.x;

    if (t < D * D) {
        #pragma unroll
        for (int m = 0; m < 5; m++) {
            const float *W, *b, *g, *be, *mu, *va;
            if (m < 3) {
                W = linW + m*D*D;  b = linb + m*D;  g = ling + m*D;
                be = linbe + m*D;  mu = linm + m*D; va = linv + m*D;
            } else {
                int l = m - 3;
                W = convW + l*D*D; b = convb + l*D; g = convg + l*D;
                be = convbe + l*D; mu = convm + l*D; va = convv + l*D;
            }
            int col = t & (D - 1);
            float sc = g[col] * rsqrtf(va[col] + 1e-5f);
            g_Wf[m*D*D + t] = W[t] * sc;
            if (t < D) g_bf[m*D + t] = (b[t] - mu[t]) * sc + be[t];
        }
    }
    if (t < 3*GMAX*D) g_max[t] = 0x007FFFFFu;   // encode(-inf)
    if (t < N) g_deg[t] = 0;
}

// -------- CSR build 1: histogram of dst --------
__global__ void hist_kernel(const int* __restrict__ ei, int E) {
    int e = blockIdx.x * blockDim.x + threadIdx.x;
    if (e < E) atomicAdd(&g_deg[ei[E + e]], 1);
}

// -------- CSR build 2a: per-tile sums (coalesced) --------
__global__ void tilesum_kernel(int N) {
    __shared__ int sm[256];
    int b = blockIdx.x, t = threadIdx.x;
    int base = b * TILE;
    int s = 0;
    for (int i = t; i < TILE; i += 256) {
        int idx = base + i;
        if (idx < N) s += g_deg[idx];
    }
    sm[t] = s;
    __syncthreads();
    for (int o = 128; o > 0; o >>= 1) {
        if (t < o) sm[t] += sm[t + o];
        __syncthreads();
    }
    if (t == 0) g_bsum[b] = sm[0];
}

// -------- CSR build 2b: 1-block scan of tile sums (NB <= 128) --------
__global__ void tilescan_kernel(int NB) {
    int t = threadIdx.x;   // 128 threads
    int v = (t < NB) ? g_bsum[t] : 0;
    // inclusive warp+block scan via shfl (128 = 4 warps)
    __shared__ int wsum[4];
    int lane = t & 31, w = t >> 5;
    int x = v;
    #pragma unroll
    for (int o = 1; o < 32; o <<= 1) {
        int y = __shfl_up_sync(0xffffffffu, x, o);
        if (lane >= o) x += y;
    }
    if (lane == 31) wsum[w] = x;
    __syncthreads();
    int add = 0;
    for (int i = 0; i < w; i++) add += wsum[i];
    if (t < NB) g_boff[t] = add + x - v;   // exclusive
}

// -------- CSR build 2c: per-tile exclusive scan + offset -> g_off, g_cur --------
__global__ void tileoff_kernel(int N, int E) {
    __shared__ int sm[TILE];
    int b = blockIdx.x, t = threadIdx.x;   // 1024 threads
    int idx = b * TILE + t;
    int v = (idx < N) ? g_deg[idx] : 0;
    sm[t] = v;
    __syncthreads();
    // Hillis-Steele inclusive scan over 1024
    for (int o = 1; o < TILE; o <<= 1) {
        int y = (t >= o) ? sm[t - o] : 0;
        __syncthreads();
        sm[t] += y;
        __syncthreads();
    }
    if (idx < N) {
        int excl = g_boff[b] + sm[t] - v;
        g_off[idx] = excl;
        g_cur[idx] = excl;
        if (idx == N - 1) g_off[N] = E;
    }
}

// -------- CSR build 3: fill src ids grouped by dst --------
__global__ void fill_kernel(const int* __restrict__ ei, int E) {
    int e = blockIdx.x * blockDim.x + threadIdx.x;
    if (e >= E) return;
    int s = ei[e];
    int d = ei[E + e];
    int pos = atomicAdd(&g_cur[d], 1);
    g_csr[pos] = s;
}

// -------- aggregation via CSR gather: g_agg[node] = sum_{s in row(node)} x[s] --------
// L=0: sources from input x (arg). L=1: sources from g_x1 (device symbol).
template <int L>
__global__ void __launch_bounds__(256)
agg_kernel(const float* __restrict__ xarg, int N) {
    const float* __restrict__ x = (L == 0) ? xarg : g_x1;
    int t = threadIdx.x;
    int node = (blockIdx.x * 256 + t) >> 5;
    int lane = t & 31;
    if (node >= N) return;

    int rs = __ldg(&g_off[node]), re = __ldg(&g_off[node + 1]);
    float acc = 0.f;
    int k = rs;
    for (; k + 8 <= re; k += 8) {
        int i0 = __ldg(&g_csr[k]),     i1 = __ldg(&g_csr[k + 1]);
        int i2 = __ldg(&g_csr[k + 2]), i3 = __ldg(&g_csr[k + 3]);
        int i4 = __ldg(&g_csr[k + 4]), i5 = __ldg(&g_csr[k + 5]);
        int i6 = __ldg(&g_csr[k + 6]), i7 = __ldg(&g_csr[k + 7]);
        float v0 = __ldg(&x[i0*D + lane]), v1 = __ldg(&x[i1*D + lane]);
        float v2 = __ldg(&x[i2*D + lane]), v3 = __ldg(&x[i3*D + lane]);
        float v4 = __ldg(&x[i4*D + lane]), v5 = __ldg(&x[i5*D + lane]);
        float v6 = __ldg(&x[i6*D + lane]), v7 = __ldg(&x[i7*D + lane]);
        acc += ((v0 + v1) + (v2 + v3)) + ((v4 + v5) + (v6 + v7));
    }
    for (; k < re; k++) acc += __ldg(&x[__ldg(&g_csr[k])*D + lane]);
    g_agg[node*D + lane] = acc;
}

// -------- fused GIN layer (aggregation precomputed in g_agg) --------
template <bool FIRST>
__global__ void __launch_bounds__(256)
fused_kernel(const float* __restrict__ xarg, float* __restrict__ xoutarg,
             const int* __restrict__ batch, const float* __restrict__ lw,
             float* __restrict__ Zbuf, int N) {
    constexpr int cm = FIRST ? 3 : 4;   // conv weight slot
    constexpr int lm = FIRST ? 1 : 2;   // lin weight slot
    __shared__ float Wc[D*D], Wl[D*D], W0[FIRST ? D*D : 1];
    __shared__ float bc[D], bl[D], b0[D];
    int t = threadIdx.x;
    for (int i = t; i < D*D; i += 256) {
        Wc[i] = g_Wf[cm*D*D + i];
        Wl[i] = g_Wf[lm*D*D + i];
        if (FIRST) W0[i] = g_Wf[i];
    }
    if (t < D) {
        bc[t] = g_bf[cm*D + t];
        bl[t] = g_bf[lm*D + t];
        if (FIRST) b0[t] = g_bf[t];
    }
    __syncthreads();

    int node = (blockIdx.x * 256 + t) >> 5;
    int lane = t & 31;
    if (node >= N) return;

    const float* xin  = FIRST ? xarg : g_x1;
    float*       xout = FIRST ? g_x1 : xoutarg;

    float xself = xin[node*D + lane];
    float acc = xself + g_agg[node*D + lane];
    int seg = batch[node];

    // ---- optional layer-0 lin-MLP on raw x ----
    float Zval = 0.f;
    if (FIRST) {
        float h0 = b0[lane];
        #pragma unroll
        for (int k = 0; k < D; k++)
            h0 = fmaf(__shfl_sync(0xffffffffu, xself, k), W0[k*D + lane], h0);
        float z0 = elu1(h0);
        Zval = lw[0] * z0;
        atomicMax(&g_max[seg*D + lane], fenc(z0));       // layer0 max over RAW z0
    }

    // ---- conv MLP: x' = ELU(BNfold(acc @ Wc)) ----
    float h = bc[lane];
    #pragma unroll
    for (int k = 0; k < D; k++)
        h = fmaf(__shfl_sync(0xffffffffu, acc, k), Wc[k*D + lane], h);
    float xn = elu1(h);
    xout[node*D + lane] = xn;

    // ---- lin MLP: z = lw * ELU(BNfold(x' @ Wl)) ----
    float h2 = bl[lane];
    #pragma unroll
    for (int k = 0; k < D; k++)
        h2 = fmaf(__shfl_sync(0xffffffffu, xn, k), Wl[k*D + lane], h2);
    constexpr int l = FIRST ? 1 : 2;
    float z = lw[l] * elu1(h2);

    if (FIRST) Zbuf[node*D + lane] = Zval + z;
    else       Zbuf[node*D + lane] += z;
    atomicMax(&g_max[l*GMAX*D + seg*D + lane], fenc(z));
}

// -------- out = sum of the three per-layer segment maxes --------
__global__ void final_kernel(float* __restrict__ out) {
    int i = blockIdx.x * blockDim.x + threadIdx.x;
    if (i < GMAX*D)
        out[i] = fdec(g_max[i]) + fdec(g_max[GMAX*D + i]) + fdec(g_max[2*GMAX*D + i]);
}

extern "C" void kernel_launch(void* const* d_in, const int* in_sizes, int n_in,
                              void* d_out, int out_size) {
    const float* x      = (const float*)d_in[0];
    const int*   ei     = (const int*)d_in[1];      // int32 (JAX x64 disabled)
    const int*   batch  = (const int*)d_in[2];
    const float* lw     = (const float*)d_in[3];
    const float* linW   = (const float*)d_in[4];
    const float* linb   = (const float*)d_in[5];
    const float* ling   = (const float*)d_in[6];
    const float* linbe  = (const float*)d_in[7];
    const float* linm   = (const float*)d_in[8];
    const float* linv   = (const float*)d_in[9];
    const float* convW  = (const float*)d_in[10];
    const float* convb  = (const float*)d_in[11];
    const float* convg  = (const float*)d_in[12];
    const float* convbe = (const float*)d_in[13];
    const float* convm  = (const float*)d_in[14];
    const float* convv  = (const float*)d_in[15];

    int N = in_sizes[0] / D;
    int E = in_sizes[1] / 2;
    int NB = (N + TILE - 1) / TILE;

    float* out = (float*)d_out;            // [G*D]
    float* Z   = out + GMAX * D;           // [N*D]
    float* xb  = Z + (size_t)N * D;        // [N*D] final x output

    int node_blocks = (N * 32 + 255) / 256;
    int e_blocks = (E + 255) / 256;
    int prep_n = N > 5*D*D ? N : 5*D*D;

    prep_kernel<<<(prep_n + 1023) / 1024, 1024>>>(linW, linb, ling, linbe, linm, linv,
                                                  convW, convb, convg, convbe, convm, convv, N);

    // CSR build (shared by both layers) — coalesced 3-phase scan
    hist_kernel<<<e_blocks, 256>>>(ei, E);
    tilesum_kernel<<<NB, 256>>>(N);
    tilescan_kernel<<<1, 128>>>(NB);
    tileoff_kernel<<<NB, TILE>>>(N, E);
    fill_kernel<<<e_blocks, 256>>>(ei, E);

    // layer 1: gather-agg(x) -> g_agg; fused l0 + conv0 + lin1 (x -> g_x1)
    agg_kernel<0><<<node_blocks, 256>>>(x, N);
    fused_kernel<true><<<node_blocks, 256>>>(x, nullptr, batch, lw, Z, N);

    // layer 2: gather-agg(g_x1) -> g_agg; fused conv1 + lin2 (g_x1 -> xb)
    agg_kernel<1><<<node_blocks, 256>>>(nullptr, N);
    fused_kernel<false><<<node_blocks, 256>>>(nullptr, xb, batch, lw, Z, N);

    final_kernel<<<(GMAX*D + 255) / 256, 256>>>(out);
}